// round 2
// baseline (speedup 1.0000x reference)
#include <cuda_runtime.h>
#include <cuda_bf16.h>

// TVConv: per-pixel spatially-varying 3x3 depthwise conv.
// x:  (B=8, C=96, H=128, W=128) fp32
// wm: (1, C, 3, 3, H, W) fp32   -- batch-invariant
// out:(B, C, H, W) fp32
//
// Strategy: thread = one (c, h, group-of-4 w). Load 9 weight float4 into
// registers ONCE, then loop b=0..7 reusing them (weights touch DRAM once).
// x rows loaded as aligned float4 + 2 halo scalars; zero padding at edges.

namespace {
constexpr int B = 8, C = 96, H = 128, W = 128;
constexpr int HW = H * W;
constexpr int W4 = W / 4;
constexpr int NTHREADS_TOTAL = C * H * W4;  // 393216
}

__global__ __launch_bounds__(256) void tvconv_kernel(
    const float* __restrict__ x,
    const float* __restrict__ wm,
    float* __restrict__ out)
{
    int idx = blockIdx.x * blockDim.x + threadIdx.x;
    if (idx >= NTHREADS_TOTAL) return;

    const int w4 = idx % W4;
    const int h  = (idx / W4) % H;
    const int c  = idx / (W4 * H);
    const int wbase = w4 * 4;

    // Load the 9 per-pixel weight vectors once; reuse for all 8 batches.
    float4 wt[9];
    const float* wp = wm + (size_t)c * 9 * HW + (size_t)h * W + wbase;
    #pragma unroll
    for (int t = 0; t < 9; t++)
        wt[t] = *reinterpret_cast<const float4*>(wp + (size_t)t * HW);

    const bool left_edge  = (w4 == 0);
    const bool right_edge = (w4 == W4 - 1);
    const bool row0_ok = (h - 1 >= 0);
    const bool row2_ok = (h + 1 < H);

    const float* xb = x + (size_t)c * HW + (size_t)h * W + wbase;
    float* ob = out + (size_t)c * HW + (size_t)h * W + wbase;

    #pragma unroll 1
    for (int b = 0; b < B; b++) {
        float acc0 = 0.f, acc1 = 0.f, acc2 = 0.f, acc3 = 0.f;

        #pragma unroll
        for (int ki = 0; ki < 3; ki++) {
            float xr0, xr1, xr2, xr3, xr4, xr5;
            bool ok = (ki == 1) || (ki == 0 ? row0_ok : row2_ok);
            if (ok) {
                const float* row = xb + (ki - 1) * W;
                float4 mid = *reinterpret_cast<const float4*>(row);
                xr1 = mid.x; xr2 = mid.y; xr3 = mid.z; xr4 = mid.w;
                xr0 = left_edge  ? 0.f : row[-1];
                xr5 = right_edge ? 0.f : row[4];
            } else {
                xr0 = xr1 = xr2 = xr3 = xr4 = xr5 = 0.f;
            }
            // kj = 0
            {
                float4 wv = wt[ki * 3 + 0];
                acc0 = fmaf(wv.x, xr0, acc0);
                acc1 = fmaf(wv.y, xr1, acc1);
                acc2 = fmaf(wv.z, xr2, acc2);
                acc3 = fmaf(wv.w, xr3, acc3);
            }
            // kj = 1
            {
                float4 wv = wt[ki * 3 + 1];
                acc0 = fmaf(wv.x, xr1, acc0);
                acc1 = fmaf(wv.y, xr2, acc1);
                acc2 = fmaf(wv.z, xr3, acc2);
                acc3 = fmaf(wv.w, xr4, acc3);
            }
            // kj = 2
            {
                float4 wv = wt[ki * 3 + 2];
                acc0 = fmaf(wv.x, xr2, acc0);
                acc1 = fmaf(wv.y, xr3, acc1);
                acc2 = fmaf(wv.z, xr4, acc2);
                acc3 = fmaf(wv.w, xr5, acc3);
            }
        }

        *reinterpret_cast<float4*>(ob) = make_float4(acc0, acc1, acc2, acc3);
        xb += (size_t)C * HW;
        ob += (size_t)C * HW;
    }
}

extern "C" void kernel_launch(void* const* d_in, const int* in_sizes, int n_in,
                              void* d_out, int out_size)
{
    const float* x  = (const float*)d_in[0];
    const float* wm = (const float*)d_in[1];
    float* out = (float*)d_out;

    const int threads = 256;
    const int blocks = (NTHREADS_TOTAL + threads - 1) / threads;  // 1536
    tvconv_kernel<<<blocks, threads>>>(x, wm, out);
}

// round 6
// speedup vs baseline: 1.4772x; 1.4772x over previous
#include <cuda_runtime.h>
#include <cuda_bf16.h>

// TVConv: per-pixel spatially-varying 3x3 depthwise conv.
// x:  (B=8, C=96, H=128, W=128) fp32
// wm: (1, C, 3, 3, H, W) fp32   -- batch-invariant
// out:(B, C, H, W) fp32
//
// v3: warp = one (c,h) row (lane == w4, W4==32 exactly).
//  - halo values come from neighbor lanes via shfl (no scalar halo loads)
//  - batch loop software-pipelined: prefetch b+1 rows while computing b
//  - wm read with __ldcs (read-once), out with __stcs (write-once):
//    keep L2 for the 3x-reused x rows.

namespace {
constexpr int B = 8, C = 96, H = 128, W = 128;
constexpr int HW = H * W;
constexpr int W4 = W / 4;                       // 32 == warp size
constexpr int NTHREADS_TOTAL = C * H * W4;      // 393216, divides 256 exactly
}

__global__ __launch_bounds__(256, 3) void tvconv_kernel(
    const float* __restrict__ x,
    const float* __restrict__ wm,
    float* __restrict__ out)
{
    const int idx = blockIdx.x * blockDim.x + threadIdx.x;
    const int lane = idx & 31;            // == w4
    const int h    = (idx >> 5) & (H - 1);
    const int c    = idx >> 12;
    const int wbase = lane * 4;

    // 9 per-pixel weight vectors, read exactly once for all 8 batches.
    float4 wt[9];
    const float* wp = wm + (size_t)c * 9 * HW + (size_t)h * W + wbase;
    #pragma unroll
    for (int t = 0; t < 9; t++)
        wt[t] = __ldcs(reinterpret_cast<const float4*>(wp + (size_t)t * HW));

    const bool row0_ok = (h > 0);
    const bool row2_ok = (h < H - 1);
    const size_t bstride = (size_t)C * HW;

    const float* xb = x + (size_t)c * HW + (size_t)h * W + wbase;
    float* ob = out + (size_t)c * HW + (size_t)h * W + wbase;

    const float4 zero4 = make_float4(0.f, 0.f, 0.f, 0.f);

    float4 cur0, cur1, cur2, nxt0, nxt1, nxt2;
    cur0 = row0_ok ? __ldg(reinterpret_cast<const float4*>(xb - W)) : zero4;
    cur1 = __ldg(reinterpret_cast<const float4*>(xb));
    cur2 = row2_ok ? __ldg(reinterpret_cast<const float4*>(xb + W)) : zero4;

    #pragma unroll 1
    for (int b = 0; b < B; b++) {
        // Prefetch next batch's 3 rows (overlaps with shfl+FMA below).
        if (b + 1 < B) {
            const float* xn = xb + (b + 1) * bstride;
            nxt0 = row0_ok ? __ldg(reinterpret_cast<const float4*>(xn - W)) : zero4;
            nxt1 = __ldg(reinterpret_cast<const float4*>(xn));
            nxt2 = row2_ok ? __ldg(reinterpret_cast<const float4*>(xn + W)) : zero4;
        }

        float acc0 = 0.f, acc1 = 0.f, acc2 = 0.f, acc3 = 0.f;

        #pragma unroll
        for (int ki = 0; ki < 3; ki++) {
            const float4 m = (ki == 0) ? cur0 : (ki == 1) ? cur1 : cur2;
            // Halo from neighbor lanes; zero at image edges.
            float xl = __shfl_up_sync(0xffffffffu, m.w, 1);
            float xr = __shfl_down_sync(0xffffffffu, m.x, 1);
            if (lane == 0)  xl = 0.f;
            if (lane == 31) xr = 0.f;

            const float4 w0 = wt[ki * 3 + 0];
            const float4 w1 = wt[ki * 3 + 1];
            const float4 w2 = wt[ki * 3 + 2];

            acc0 = fmaf(w0.x, xl,  acc0);
            acc1 = fmaf(w0.y, m.x, acc1);
            acc2 = fmaf(w0.z, m.y, acc2);
            acc3 = fmaf(w0.w, m.z, acc3);

            acc0 = fmaf(w1.x, m.x, acc0);
            acc1 = fmaf(w1.y, m.y, acc1);
            acc2 = fmaf(w1.z, m.z, acc2);
            acc3 = fmaf(w1.w, m.w, acc3);

            acc0 = fmaf(w2.x, m.y, acc0);
            acc1 = fmaf(w2.y, m.z, acc1);
            acc2 = fmaf(w2.z, m.w, acc2);
            acc3 = fmaf(w2.w, xr,  acc3);
        }

        __stcs(reinterpret_cast<float4*>(ob + b * bstride),
               make_float4(acc0, acc1, acc2, acc3));

        cur0 = nxt0; cur1 = nxt1; cur2 = nxt2;
    }
}

extern "C" void kernel_launch(void* const* d_in, const int* in_sizes, int n_in,
                              void* d_out, int out_size)
{
    const float* x  = (const float*)d_in[0];
    const float* wm = (const float*)d_in[1];
    float* out = (float*)d_out;

    const int threads = 256;
    const int blocks = NTHREADS_TOTAL / threads;  // 1536, exact
    tvconv_kernel<<<blocks, threads>>>(x, wm, out);
}